// round 9
// baseline (speedup 1.0000x reference)
#include <cuda_runtime.h>
#include <cuda_bf16.h>
#include <stdint.h>

#define M_PAIRS 4096
#define T_LEN   512
#define D_DIM   512
#define N_CAND  65
#define SPAN    4094u

#define NBLK      296                 // 2 per SM on 148 SMs — wave-1 resident
#define NTHR      256                 // 8 warps
#define NWARP_TOT (NBLK * 8)          // 2368 warps; rows w and w+2368

// Device scratch (no allocations). Zero-init at load; sync state self-resets.
__device__ __nv_bfloat16 g_enc [M_PAIRS * D_DIM];
__device__ float         g_pred[M_PAIRS * D_DIM];
__device__ float         g_rowloss[M_PAIRS];
__device__ float         g_rowacc [M_PAIRS];
__device__ unsigned int  g_cnt1[32];      // phase-boundary tree, level 1
__device__ unsigned int  g_cnt2;          // phase-boundary tree, level 2
__device__ unsigned int  g_release;       // phase-boundary release flag
__device__ unsigned int  g_cnt3[32];      // final tree, level 1
__device__ unsigned int  g_cnt4;          // final tree, level 2

// ---------------- Threefry-2x32 (20 rounds), exact JAX semantics ------------
struct TFK { uint32_t a, b; };

__host__ __device__ constexpr TFK tf2x32_c(uint32_t k0, uint32_t k1,
                                           uint32_t x0, uint32_t x1) {
    uint32_t ks2 = 0x1BD11BDAu ^ k0 ^ k1;
    x0 += k0; x1 += k1;
#define TF_RND(R) { x0 += x1; x1 = (x1 << (R)) | (x1 >> (32 - (R))); x1 ^= x0; }
    TF_RND(13) TF_RND(15) TF_RND(26) TF_RND(6)
    x0 += k1;  x1 += ks2 + 1u;
    TF_RND(17) TF_RND(29) TF_RND(16) TF_RND(24)
    x0 += ks2; x1 += k0 + 2u;
    TF_RND(13) TF_RND(15) TF_RND(26) TF_RND(6)
    x0 += k0;  x1 += k1 + 3u;
    TF_RND(17) TF_RND(29) TF_RND(16) TF_RND(24)
    x0 += k1;  x1 += ks2 + 4u;
    TF_RND(13) TF_RND(15) TF_RND(26) TF_RND(6)
    x0 += ks2; x1 += k0 + 5u;
#undef TF_RND
    return TFK{x0, x1};
}

__device__ constexpr TFK SK1 = tf2x32_c(0u, 42u, 0u, 0u);  // split(key(42))[0]
__device__ constexpr TFK SK2 = tf2x32_c(0u, 42u, 0u, 1u);  // split(key(42))[1]

__device__ __forceinline__ int tf_negative(int m, int n, int is64) {
    uint32_t t = (uint32_t)m * 64u + (uint32_t)n;
    TFK A = tf2x32_c(SK1.a, SK1.b, 0u, t);
    TFK B = tf2x32_c(SK2.a, SK2.b, 0u, t);
    uint32_t r;
    if (!is64) {
        uint32_t hi = A.a ^ A.b, lo = B.a ^ B.b;
        r = ((hi % SPAN) * 1024u + (lo % SPAN)) % SPAN;
    } else {
        unsigned long long hi = (((unsigned long long)A.a) << 32) | A.b;
        unsigned long long lo = (((unsigned long long)B.a) << 32) | B.b;
        r = (uint32_t)(((hi % 4094ull) * 512ull + (lo % 4094ull)) % 4094ull);
    }
    return (int)r + (((int)r >= m) ? 1 : 0);
}

// ---------------- packed f32x2 helpers ---------------------------------------
__device__ __forceinline__ void bfma2(unsigned long long& acc, uint32_t u,
                                      unsigned long long p2) {
    asm("{\n\t"
        ".reg .b32 lo, hi;\n\t"
        ".reg .b64 e;\n\t"
        "shl.b32 lo, %1, 16;\n\t"
        "and.b32 hi, %1, 0xFFFF0000;\n\t"
        "mov.b64 e, {lo, hi};\n\t"
        "fma.rn.f32x2 %0, e, %2, %0;\n\t"
        "}" : "+l"(acc) : "r"(u), "l"(p2));
}
__device__ __forceinline__ unsigned long long packf2(float lo, float hi) {
    unsigned long long r;
    asm("mov.b64 %0, {%1, %2};" : "=l"(r) : "f"(lo), "f"(hi));
    return r;
}
__device__ __forceinline__ float hadd2(unsigned long long a) {
    float lo, hi;
    asm("mov.b64 {%0, %1}, %2;" : "=f"(lo), "=f"(hi) : "l"(a));
    return lo + hi;
}
__device__ __forceinline__ float dot8(uint4 v0, uint4 v1,
                                      const unsigned long long p2[8]) {
    unsigned long long acc = 0ull;
    bfma2(acc, v0.x, p2[0]);  bfma2(acc, v0.y, p2[1]);
    bfma2(acc, v0.z, p2[2]);  bfma2(acc, v0.w, p2[3]);
    bfma2(acc, v1.x, p2[4]);  bfma2(acc, v1.y, p2[5]);
    bfma2(acc, v1.z, p2[6]);  bfma2(acc, v1.w, p2[7]);
    return hadd2(acc);
}

// ---------------- fused persistent kernel ------------------------------------
__global__ void __launch_bounds__(NTHR, 2)
fused_kernel(const float* __restrict__ pred,
             const float* __restrict__ enc,
             const void*  __restrict__ mask,
             float* __restrict__ out, int out_size) {
    const int tid  = threadIdx.x;
    const int warp = tid >> 5, lane = tid & 31;
    const int bid  = blockIdx.x;
    const int wgid = bid * 8 + warp;
    const unsigned FULL = 0xFFFFFFFFu;

    // ---- dtype probe (per warp, fixed 512B window, L2-broadcast) ----
    int4 pw = ((const int4*)mask)[lane];
    unsigned any = __ballot_sync(FULL, (pw.y | pw.w) != 0);
    const int is64 = (any == 0u) ? 1 : 0;

    // negatives for this warp's rows: lane holds neg 2*lane, 2*lane+1
    int s0[2], s1[2];

    // =================== Phase 1: gather + normalize + PRNG ===================
    #pragma unroll
    for (int s = 0; s < 2; s++) {
        int r = wgid + s * NWARP_TOT;
        if (r >= M_PAIRS) break;

        s0[s] = tf_negative(r, 2 * lane,     is64);
        s1[s] = tf_negative(r, 2 * lane + 1, is64);

        long long row, col;
        if (is64) {
            const long long* mm = (const long long*)mask;
            row = mm[2 * r]; col = mm[2 * r + 1];
        } else {
            const int* mm = (const int*)mask;
            row = mm[2 * r]; col = mm[2 * r + 1];
        }
        long long base = (row * (long long)T_LEN + col) * (long long)D_DIM;

        const float4* se = (const float4*)(enc  + base);
        const float4* sp = (const float4*)(pred + base);
        float4 e[4], p[4];
        #pragma unroll
        for (int j = 0; j < 4; j++) { e[j] = se[lane + 32 * j]; }
        #pragma unroll
        for (int j = 0; j < 4; j++) { p[j] = sp[lane + 32 * j]; }

        float sse = 0.0f, ssp = 0.0f;
        #pragma unroll
        for (int j = 0; j < 4; j++) {
            sse += e[j].x*e[j].x + e[j].y*e[j].y + e[j].z*e[j].z + e[j].w*e[j].w;
            ssp += p[j].x*p[j].x + p[j].y*p[j].y + p[j].z*p[j].z + p[j].w*p[j].w;
        }
        #pragma unroll
        for (int o = 16; o; o >>= 1) {
            sse += __shfl_xor_sync(FULL, sse, o);
            ssp += __shfl_xor_sync(FULL, ssp, o);
        }
        float invE = 1.0f / fmaxf(sqrtf(sse), 1e-12f);
        float invP = 1.0f / fmaxf(sqrtf(ssp), 1e-12f);

        uint2*  de = (uint2*)(g_enc  + (size_t)r * D_DIM);
        float4* dp = (float4*)(g_pred + (size_t)r * D_DIM);
        #pragma unroll
        for (int j = 0; j < 4; j++) {
            __nv_bfloat162 b0 = __floats2bfloat162_rn(e[j].x * invE, e[j].y * invE);
            __nv_bfloat162 b1 = __floats2bfloat162_rn(e[j].z * invE, e[j].w * invE);
            de[lane + 32 * j] = make_uint2(*reinterpret_cast<uint32_t*>(&b0),
                                           *reinterpret_cast<uint32_t*>(&b1));
            dp[lane + 32 * j] = make_float4(p[j].x * invP, p[j].y * invP,
                                            p[j].z * invP, p[j].w * invP);
        }
    }

    // =================== grid-wide sync (release-acquire) =====================
    __syncthreads();
    if (tid == 0) {
        __threadfence();
        int idx = bid & 31;
        unsigned thr = (idx < 8) ? 10u : 9u;          // 8*10 + 24*9 = 296
        if (atomicAdd(&g_cnt1[idx], 1u) == thr - 1u)
            if (atomicAdd(&g_cnt2, 1u) == 31u)
                atomicExch(&g_release, 1u);
        volatile unsigned* rel = &g_release;
        while (*rel == 0u) __nanosleep(64);
        __threadfence();
    }
    __syncthreads();

    // =================== Phase 2: per-warp sims + LSE ==========================
    #pragma unroll 1
    for (int s = 0; s < 2; s++) {
        int r = wgid + s * NWARP_TOT;
        if (r >= M_PAIRS) break;

        // pred row as 8 packed f32x2 (elements [8*lane, 8*lane+8) + [256+...])
        unsigned long long p2[8];
        {
            const float4* p4 = (const float4*)(g_pred + (size_t)r * D_DIM);
            #pragma unroll
            for (int j = 0; j < 2; j++) {
                float4 a = p4[j * 64 + lane * 2];
                float4 b = p4[j * 64 + lane * 2 + 1];
                p2[j*4 + 0] = packf2(a.x, a.y);
                p2[j*4 + 1] = packf2(a.z, a.w);
                p2[j*4 + 2] = packf2(b.x, b.y);
                p2[j*4 + 3] = packf2(b.z, b.w);
            }
        }

        // candidate index: c==0 -> r; c>=1 -> negative c-1 at lane (c-1)>>1
        float kA = 0.0f, kB = 0.0f, kC = 0.0f;   // lane k: cands 2k, 2k+1; lane0: 64

        // software pipeline over 32 pairs + tail, 2 pairs in flight
        int i0 = r;
        int i1 = __shfl_sync(FULL, s0[s], 0);
        const uint4* eA = (const uint4*)(g_enc + (size_t)i0 * D_DIM);
        const uint4* eB = (const uint4*)(g_enc + (size_t)i1 * D_DIM);
        uint4 a0 = eA[lane], a1 = eA[32 + lane];
        uint4 b0 = eB[lane], b1 = eB[32 + lane];

        #pragma unroll 1
        for (int c = 0; c < 64; c += 2) {
            uint4 na0, na1, nb0, nb1;
            if (c < 62) {
                int n0 = __shfl_sync(FULL, s1[s], c >> 1);        // cand c+2 (neg c+1)
                int n1 = __shfl_sync(FULL, s0[s], (c >> 1) + 1);  // cand c+3 (neg c+2)
                const uint4* nA = (const uint4*)(g_enc + (size_t)n0 * D_DIM);
                const uint4* nB = (const uint4*)(g_enc + (size_t)n1 * D_DIM);
                na0 = nA[lane]; na1 = nA[32 + lane];
                nb0 = nB[lane]; nb1 = nB[32 + lane];
            } else {
                int nT = __shfl_sync(FULL, s1[s], 31);            // cand 64 (neg 63)
                const uint4* nA = (const uint4*)(g_enc + (size_t)nT * D_DIM);
                na0 = nA[lane]; na1 = nA[32 + lane];
            }
            float d0 = dot8(a0, a1, p2);
            float d1 = dot8(b0, b1, p2);
            #pragma unroll
            for (int o = 16; o; o >>= 1) {
                d0 += __shfl_xor_sync(FULL, d0, o);
                d1 += __shfl_xor_sync(FULL, d1, o);
            }
            if (lane == (c >> 1)) { kA = d0 * 10.0f; kB = d1 * 10.0f; }
            a0 = na0; a1 = na1; b0 = nb0; b1 = nb1;
        }
        {   // tail: candidate 64 (data already in a0/a1)
            float d = dot8(a0, a1, p2);
            #pragma unroll
            for (int o = 16; o; o >>= 1) d += __shfl_xor_sync(FULL, d, o);
            if (lane == 0) kC = d * 10.0f;
        }

        // warp-level LSE / argmax
        float v2 = (lane == 0) ? kC : -3.4e38f;
        float mx = fmaxf(fmaxf(kA, kB), v2);
        #pragma unroll
        for (int o = 16; o; o >>= 1) mx = fmaxf(mx, __shfl_xor_sync(FULL, mx, o));
        float ss = expf(kA - mx) + expf(kB - mx) + ((lane == 0) ? expf(kC - mx) : 0.0f);
        #pragma unroll
        for (int o = 16; o; o >>= 1) ss += __shfl_xor_sync(FULL, ss, o);
        float sim0 = __shfl_sync(FULL, kA, 0);
        if (lane == 0) {
            g_rowloss[r] = mx + logf(ss) - sim0;
            g_rowacc[r]  = (sim0 >= mx) ? 1.0f : 0.0f;
        }
    }

    // =================== final arrival tree + fused reduce ====================
    __shared__ bool last;
    __syncthreads();
    __threadfence();
    if (tid == 0) {
        bool l = false;
        int idx = bid & 31;
        unsigned thr = (idx < 8) ? 10u : 9u;
        if (atomicAdd(&g_cnt3[idx], 1u) == thr - 1u)
            if (atomicAdd(&g_cnt4, 1u) == 31u) l = true;
        last = l;
    }
    __syncthreads();
    if (!last) return;
    __threadfence();

    // reset all sync state for next graph replay (everyone else has passed)
    if (tid < 32) { g_cnt1[tid] = 0u; g_cnt3[tid] = 0u; }
    if (tid == 32) g_cnt2 = 0u;
    if (tid == 33) g_cnt4 = 0u;
    if (tid == 34) g_release = 0u;

    float sl = 0.0f, sa = 0.0f;
    #pragma unroll
    for (int k = 0; k < M_PAIRS / NTHR; k++) {
        int i = k * NTHR + tid;
        sl += g_rowloss[i];
        sa += g_rowacc[i];
    }
    __shared__ float bl[8], ba[8];
    #pragma unroll
    for (int o = 16; o; o >>= 1) {
        sl += __shfl_xor_sync(FULL, sl, o);
        sa += __shfl_xor_sync(FULL, sa, o);
    }
    if (lane == 0) { bl[warp] = sl; ba[warp] = sa; }
    __syncthreads();
    if (tid == 0) {
        float tl = 0.0f, ta = 0.0f;
        #pragma unroll
        for (int w = 0; w < 8; w++) { tl += bl[w]; ta += ba[w]; }
        out[0] = tl / (float)M_PAIRS;
        if (out_size > 1) out[1] = ta / (float)M_PAIRS;
    }
}

// ---------------- Launch ----------------------------------------------------
extern "C" void kernel_launch(void* const* d_in, const int* in_sizes, int n_in,
                              void* d_out, int out_size) {
    const float* pred = (const float*)d_in[0];
    const float* enc  = (const float*)d_in[1];
    const void*  mask = d_in[2];

    fused_kernel<<<NBLK, NTHR>>>(pred, enc, mask, (float*)d_out, out_size);
}